// round 15
// baseline (speedup 1.0000x reference)
#include <cuda_runtime.h>
#include <cuda_bf16.h>
#include <cstdint>
#include <math.h>

#define NB   4      // batch pairs (B)
#define NPT  4096   // points per cloud (N)
#define CF   640    // feature dim (C)
#define INV_N (1.0f/4096.0f)

#define BKC  16
#define NKC  (CF/BKC)    // 40 k-chunks of 16
#define CSLOTS 256

// -------- scratch (device globals; no allocation allowed) --------
__device__ __nv_bfloat16 g_fhi[(size_t)2*NB*NPT*CF];  // bf16 hi part of normalized feats
__device__ __nv_bfloat16 g_flo[(size_t)2*NB*NPT*CF];  // bf16 lo residual
__device__ float g_K[(size_t)NB*NPT*NPT];              // exp kernel fp32, 256 MB (final pass)
__device__ __nv_bfloat16 g_Kh[(size_t)NB*NPT*NPT];     // exp kernel bf16, 128 MB (sinkhorn)
__device__ float g_cs[(size_t)NB*CSLOTS*NPT];          // KTa partials, 16 MB
__device__ float g_b[NB*NPT];
__device__ float g_rowsum[NB*NPT];

__device__ __forceinline__ uint32_t smem_u32(const void* p) {
    uint32_t a;
    asm("{ .reg .u64 t; cvta.to.shared.u64 t, %1; cvt.u32.u64 %0, t; }" : "=r"(a) : "l"(p));
    return a;
}

// -------- 1) fused prep: norm + transpose + bf16 hi/lo split --------
#define PRE_SMEM (32 * 641 * 4)
__global__ __launch_bounds__(256) void prep_kernel(const float* __restrict__ pf) {
    extern __shared__ float ps[];           // [32][641] padded
    __shared__ float partial[256];
    __shared__ float invs[32];
    int bb = blockIdx.y;
    int n0 = blockIdx.x * 32;
    int tid = threadIdx.x;
    int tx = tid & 31, ty = tid >> 5;
    float ss = 0.f;
    for (int c = ty; c < CF; c += 8) {
        float v = pf[((size_t)bb * CF + c) * NPT + n0 + tx];
        ps[tx * 641 + c] = v;
        ss += v * v;
    }
    partial[tid] = ss;
    __syncthreads();
    if (tid < 32) {
        float s = 0.f;
        #pragma unroll
        for (int g = 0; g < 8; g++) s += partial[g * 32 + tid];
        invs[tid] = 1.0f / sqrtf(s + 1e-8f);
    }
    __syncthreads();
    for (int idx = tid; idx < 32 * 320; idx += 256) {
        int n  = idx / 320;
        int cp = (idx - n * 320) * 2;
        float inv = invs[n];
        float v0 = ps[n * 641 + cp] * inv;
        float v1 = ps[n * 641 + cp + 1] * inv;
        __nv_bfloat16 h0 = __float2bfloat16(v0);
        __nv_bfloat16 h1 = __float2bfloat16(v1);
        float r0 = v0 - __bfloat162float(h0);
        float r1 = v1 - __bfloat162float(h1);
        size_t o = ((size_t)bb * NPT + n0 + n) * CF + cp;
        *(__nv_bfloat162*)(g_fhi + o) = __halves2bfloat162(h0, h1);
        *(__nv_bfloat162*)(g_flo + o) = __halves2bfloat162(__float2bfloat16(r0), __float2bfloat16(r1));
    }
}

// -------- 2) split-bf16 mma.sync GEMM + exp epilogue + KTa0 column sums --------
#define TILE_B   6144
#define STAGE_B  24576
#define NSTAGE   3
#define SMEM_DYN (NSTAGE * STAGE_B)
__global__ __launch_bounds__(256, 2) void gemm_mma_kernel(const float* __restrict__ eps_p) {
    extern __shared__ __align__(128) char sm[];
    int tid  = threadIdx.x;
    int wid  = tid >> 5, lane = tid & 31;
    int b    = blockIdx.z;
    int row0 = blockIdx.y * 128;
    int col0 = blockIdx.x * 128;
    size_t offA = (size_t)b * NPT * CF;
    size_t offB = (size_t)(b + NB) * NPT * CF;
    uint32_t sbase = smem_u32(sm);

    int lr = tid >> 1, lq = tid & 1;
    uint32_t rowoff = lr * 48 + lq * 16;
    auto load_stage = [&](int kc, int s) {
        uint32_t st = sbase + s * STAGE_B;
        size_t gA = offA + (size_t)(row0 + lr) * CF + kc * BKC + lq * 8;
        size_t gB = offB + (size_t)(col0 + lr) * CF + kc * BKC + lq * 8;
        asm volatile("cp.async.cg.shared.global [%0], [%1], 16;" :: "r"(st + rowoff),              "l"((const void*)(g_fhi + gA)));
        asm volatile("cp.async.cg.shared.global [%0], [%1], 16;" :: "r"(st + TILE_B + rowoff),     "l"((const void*)(g_flo + gA)));
        asm volatile("cp.async.cg.shared.global [%0], [%1], 16;" :: "r"(st + 2 * TILE_B + rowoff), "l"((const void*)(g_fhi + gB)));
        asm volatile("cp.async.cg.shared.global [%0], [%1], 16;" :: "r"(st + 3 * TILE_B + rowoff), "l"((const void*)(g_flo + gB)));
        asm volatile("cp.async.commit_group;" ::: "memory");
    };

    float acc[2][8][4];
    #pragma unroll
    for (int mt = 0; mt < 2; mt++)
        #pragma unroll
        for (int nt = 0; nt < 8; nt++)
            #pragma unroll
            for (int k = 0; k < 4; k++) acc[mt][nt][k] = 0.f;

    int warp_m = wid & 3, warp_n = wid >> 2;
    int p = lane >> 3, r8 = lane & 7;
    int arow = warp_m * 32 + (p & 1) * 8 + r8;
    int aq   = (p >> 1);
    int brow = warp_n * 64 + (p >> 1) * 8 + r8;
    int bq   = (p & 1);

    load_stage(0, 0);
    load_stage(1, 1);
    for (int kc = 0; kc < NKC; kc++) {
        if (kc + 1 < NKC) {
            asm volatile("cp.async.wait_group 1;" ::: "memory");
        } else {
            asm volatile("cp.async.wait_group 0;" ::: "memory");
        }
        __syncthreads();
        if (kc + 2 < NKC) load_stage(kc + 2, (kc + 2) % NSTAGE);
        uint32_t st = sbase + (kc % NSTAGE) * STAGE_B;

        uint32_t ah[2][4], al[2][4];
        #pragma unroll
        for (int mt = 0; mt < 2; mt++) {
            uint32_t ad = st + (arow + mt * 16) * 48 + aq * 16;
            asm volatile("ldmatrix.sync.aligned.m8n8.x4.shared.b16 {%0,%1,%2,%3}, [%4];"
                : "=r"(ah[mt][0]), "=r"(ah[mt][1]), "=r"(ah[mt][2]), "=r"(ah[mt][3]) : "r"(ad));
            asm volatile("ldmatrix.sync.aligned.m8n8.x4.shared.b16 {%0,%1,%2,%3}, [%4];"
                : "=r"(al[mt][0]), "=r"(al[mt][1]), "=r"(al[mt][2]), "=r"(al[mt][3]) : "r"(ad + TILE_B));
        }
        uint32_t bh[8][2], bl[8][2];
        #pragma unroll
        for (int np = 0; np < 4; np++) {
            uint32_t bd = st + 2 * TILE_B + (brow + np * 16) * 48 + bq * 16;
            uint32_t t0, t1, t2, t3;
            asm volatile("ldmatrix.sync.aligned.m8n8.x4.shared.b16 {%0,%1,%2,%3}, [%4];"
                : "=r"(t0), "=r"(t1), "=r"(t2), "=r"(t3) : "r"(bd));
            bh[2 * np][0] = t0; bh[2 * np][1] = t1;
            bh[2 * np + 1][0] = t2; bh[2 * np + 1][1] = t3;
            asm volatile("ldmatrix.sync.aligned.m8n8.x4.shared.b16 {%0,%1,%2,%3}, [%4];"
                : "=r"(t0), "=r"(t1), "=r"(t2), "=r"(t3) : "r"(bd + TILE_B));
            bl[2 * np][0] = t0; bl[2 * np][1] = t1;
            bl[2 * np + 1][0] = t2; bl[2 * np + 1][1] = t3;
        }
        #pragma unroll
        for (int mt = 0; mt < 2; mt++)
            #pragma unroll
            for (int nt = 0; nt < 8; nt++)
                asm volatile("mma.sync.aligned.m16n8k16.row.col.f32.bf16.bf16.f32 "
                    "{%0,%1,%2,%3}, {%4,%5,%6,%7}, {%8,%9}, {%0,%1,%2,%3};"
                    : "+f"(acc[mt][nt][0]), "+f"(acc[mt][nt][1]), "+f"(acc[mt][nt][2]), "+f"(acc[mt][nt][3])
                    : "r"(ah[mt][0]), "r"(ah[mt][1]), "r"(ah[mt][2]), "r"(ah[mt][3]),
                      "r"(bh[nt][0]), "r"(bh[nt][1]));
        #pragma unroll
        for (int mt = 0; mt < 2; mt++)
            #pragma unroll
            for (int nt = 0; nt < 8; nt++)
                asm volatile("mma.sync.aligned.m16n8k16.row.col.f32.bf16.bf16.f32 "
                    "{%0,%1,%2,%3}, {%4,%5,%6,%7}, {%8,%9}, {%0,%1,%2,%3};"
                    : "+f"(acc[mt][nt][0]), "+f"(acc[mt][nt][1]), "+f"(acc[mt][nt][2]), "+f"(acc[mt][nt][3])
                    : "r"(ah[mt][0]), "r"(ah[mt][1]), "r"(ah[mt][2]), "r"(ah[mt][3]),
                      "r"(bl[nt][0]), "r"(bl[nt][1]));
        #pragma unroll
        for (int mt = 0; mt < 2; mt++)
            #pragma unroll
            for (int nt = 0; nt < 8; nt++)
                asm volatile("mma.sync.aligned.m16n8k16.row.col.f32.bf16.bf16.f32 "
                    "{%0,%1,%2,%3}, {%4,%5,%6,%7}, {%8,%9}, {%0,%1,%2,%3};"
                    : "+f"(acc[mt][nt][0]), "+f"(acc[mt][nt][1]), "+f"(acc[mt][nt][2]), "+f"(acc[mt][nt][3])
                    : "r"(al[mt][0]), "r"(al[mt][1]), "r"(al[mt][2]), "r"(al[mt][3]),
                      "r"(bh[nt][0]), "r"(bh[nt][1]));
    }

    // epilogue: exp -> fp32 K + bf16 K + per-thread column partials
    float eps = expf(eps_p[0]) + 0.03f;
    float inv_eps = 1.0f / eps;
    int gam = lane >> 2, lam = lane & 3;
    float csum[16];
    #pragma unroll
    for (int k = 0; k < 16; k++) csum[k] = 0.f;
    #pragma unroll
    for (int mt = 0; mt < 2; mt++) {
        #pragma unroll
        for (int half = 0; half < 2; half++) {
            int grow = row0 + warp_m * 32 + mt * 16 + half * 8 + gam;
            size_t base = ((size_t)b * NPT + grow) * NPT + col0 + warp_n * 64;
            float* Kout = g_K + base;
            __nv_bfloat16* Khout = g_Kh + base;
            #pragma unroll
            for (int nt = 0; nt < 8; nt++) {
                float e0 = __expf((acc[mt][nt][2 * half + 0] - 1.0f) * inv_eps);
                float e1 = __expf((acc[mt][nt][2 * half + 1] - 1.0f) * inv_eps);
                int c = nt * 8 + lam * 2;
                *(float2*)(Kout + c) = make_float2(e0, e1);
                *(__nv_bfloat162*)(Khout + c) = __floats2bfloat162_rn(e0, e1);
                csum[nt * 2 + 0] += e0;
                csum[nt * 2 + 1] += e1;
            }
        }
    }
    __syncthreads();
    float* colpart = (float*)sm;           // [256][17]
    #pragma unroll
    for (int k = 0; k < 16; k++) colpart[tid * 17 + k] = csum[k];
    __syncthreads();
    if (tid < 128) {
        int cc = tid;
        int wnc = cc >> 6;
        int rem = cc & 63;
        int ntc = rem >> 3;
        int lamc = (rem & 7) >> 1;
        int jc = rem & 1;
        float s = 0.f;
        #pragma unroll
        for (int wm = 0; wm < 4; wm++)
            #pragma unroll
            for (int gm = 0; gm < 8; gm++)
                s += colpart[((wnc * 4 + wm) * 32 + gm * 4 + lamc) * 17 + ntc * 2 + jc];
        g_cs[((size_t)b * CSLOTS + blockIdx.y) * NPT + col0 + cc] = s * INV_N;
    }
}

// -------- 3) update b from KTa partials (compile-time trip count) --------
template <int NP>
__global__ __launch_bounds__(256) void update_b_kernel(const float* __restrict__ gamma_p,
                                                       const float* __restrict__ eps_p) {
    int b = blockIdx.y;
    int m = blockIdx.x * 256 + threadIdx.x;
    const float* cs = g_cs + (size_t)b * CSLOTS * NPT + m;
    float s = 0.f;
    #pragma unroll
    for (int pp = 0; pp < NP; pp++) s += cs[(size_t)pp * NPT];
    float eps = expf(eps_p[0]) + 0.03f;
    float gam = expf(gamma_p[0]);
    float pw  = gam / (gam + eps);
    g_b[b * NPT + m] = powf(INV_N / (s + 1e-8f), pw);
}

// -------- 4) fused Kb -> a -> KTa partials (bf16 K, 16 rows per block) --------
__global__ __launch_bounds__(256) void fused_kb_kta_kernel(const float* __restrict__ gamma_p,
                                                           const float* __restrict__ eps_p) {
    __shared__ float acc[4096];
    __shared__ float wred[8];
    __shared__ float a_sh[4];
    int b = blockIdx.y;
    int n0 = blockIdx.x * 16;
    int tid = threadIdx.x;
    int warp = tid >> 5, lane = tid & 31;
    const float* bv = g_b + b * NPT;
    float eps = expf(eps_p[0]) + 0.03f;
    float gmv = expf(gamma_p[0]);
    float pw  = gmv / (gmv + eps);

    #pragma unroll
    for (int i = 0; i < 16; i++) acc[tid + i * 256] = 0.f;
    __syncthreads();

    for (int g = 0; g < 4; g++) {
        {
            int n = n0 + g * 4 + (warp >> 1);
            int half = warp & 1;
            const __nv_bfloat16* Krow = g_Kh + ((size_t)b * NPT + n) * NPT + half * 2048;
            const float* bvh = bv + half * 2048;
            float s = 0.f;
            #pragma unroll
            for (int j = 0; j < 8; j++) {
                int m = (j * 32 + lane) * 8;
                uint4 kv = *(const uint4*)(Krow + m);
                const __nv_bfloat162* kp = (const __nv_bfloat162*)&kv;
                float4 b0 = *(const float4*)(bvh + m);
                float4 b1 = *(const float4*)(bvh + m + 4);
                float2 k0 = __bfloat1622float2(kp[0]);
                float2 k1 = __bfloat1622float2(kp[1]);
                float2 k2 = __bfloat1622float2(kp[2]);
                float2 k3 = __bfloat1622float2(kp[3]);
                s += k0.x * b0.x + k0.y * b0.y + k1.x * b0.z + k1.y * b0.w;
                s += k2.x * b1.x + k2.y * b1.y + k3.x * b1.z + k3.y * b1.w;
            }
            #pragma unroll
            for (int o = 16; o > 0; o >>= 1) s += __shfl_xor_sync(0xFFFFFFFFu, s, o);
            if (lane == 0) wred[warp] = s;
        }
        __syncthreads();
        if (tid < 4) {
            float kb = wred[2 * tid] + wred[2 * tid + 1];
            a_sh[tid] = powf(INV_N / (kb + 1e-8f), pw);
        }
        __syncthreads();
        #pragma unroll
        for (int r = 0; r < 4; r++) {
            int n = n0 + g * 4 + r;
            float an = a_sh[r];
            const __nv_bfloat16* Krow = g_Kh + ((size_t)b * NPT + n) * NPT;
            #pragma unroll
            for (int j = 0; j < 4; j++) {
                int c = warp * 512 + j * 128 + lane * 4;
                uint2 kv = *(const uint2*)(Krow + c);
                const __nv_bfloat162* kp = (const __nv_bfloat162*)&kv;
                float2 k0 = __bfloat1622float2(kp[0]);
                float2 k1 = __bfloat1622float2(kp[1]);
                float4 av = *(float4*)(acc + c);
                av.x += an * k0.x; av.y += an * k0.y;
                av.z += an * k1.x; av.w += an * k1.y;
                *(float4*)(acc + c) = av;
            }
        }
        __syncthreads();
    }
    float* dst = g_cs + ((size_t)b * CSLOTS + blockIdx.x) * NPT;
    #pragma unroll
    for (int i = 0; i < 16; i++) dst[tid + i * 256] = acc[tid + i * 256];
}

// -------- 5) fused: last Kb + a-update + T + row_sum + matches --------
#define FIN_SMEM (3 * NPT * 4)
__global__ __launch_bounds__(256) void kb_final_kernel(const float* __restrict__ gamma_p,
                                                       const float* __restrict__ eps_p,
                                                       const float* __restrict__ coords,
                                                       float* __restrict__ out) {
    extern __shared__ float cs3[];           // [3][NPT]: y, z, w
    __shared__ float wred[8];
    __shared__ float wred3[8][3];
    __shared__ float a_sh, kb_sh;
    int b = blockIdx.y;
    int tid = threadIdx.x;
    int warp = tid >> 5, lane = tid & 31;
    const float* bv = g_b + b * NPT;
    const float* c2 = coords + (size_t)(NB + b) * NPT * 4;

    for (int idx = tid; idx < NPT; idx += 256) {
        float4 cc = *(const float4*)(c2 + (size_t)idx * 4);
        cs3[idx] = cc.y;
        cs3[NPT + idx] = cc.z;
        cs3[2 * NPT + idx] = cc.w;
    }
    float4 br[4];
    #pragma unroll
    for (int i = 0; i < 4; i++) br[i] = *(const float4*)(bv + tid * 4 + i * 1024);
    __syncthreads();

    float eps = expf(eps_p[0]) + 0.03f;
    float gmv = expf(gamma_p[0]);
    float pw  = gmv / (gmv + eps);

    for (int r = 0; r < 4; r++) {
        int n = blockIdx.x * 4 + r;
        const float* Krow = g_K + ((size_t)b * NPT + n) * NPT;
        float4 kr[4];
        float s = 0.f;
        #pragma unroll
        for (int i = 0; i < 4; i++) {
            int m = tid * 4 + i * 1024;
            kr[i] = __ldcs((const float4*)(Krow + m));
            s += kr[i].x * br[i].x + kr[i].y * br[i].y + kr[i].z * br[i].z + kr[i].w * br[i].w;
        }
        #pragma unroll
        for (int o = 16; o > 0; o >>= 1) s += __shfl_xor_sync(0xFFFFFFFFu, s, o);
        if (lane == 0) wred[warp] = s;
        __syncthreads();
        if (tid == 0) {
            float kb = 0.f;
            #pragma unroll
            for (int w = 0; w < 8; w++) kb += wred[w];
            kb_sh = kb;
            a_sh  = powf(INV_N / (kb + 1e-8f), pw);
        }
        __syncthreads();
        float a = a_sh;
        float* Trow = out + ((size_t)b * NPT + n) * NPT;
        float mx = 0.f, my = 0.f, mz = 0.f;
        #pragma unroll
        for (int i = 0; i < 4; i++) {
            int m = tid * 4 + i * 1024;
            float4 t;
            t.x = a * kr[i].x * br[i].x;
            t.y = a * kr[i].y * br[i].y;
            t.z = a * kr[i].z * br[i].z;
            t.w = a * kr[i].w * br[i].w;
            __stcs((float4*)(Trow + m), t);
            mx += t.x * cs3[m] + t.y * cs3[m + 1] + t.z * cs3[m + 2] + t.w * cs3[m + 3];
            my += t.x * cs3[NPT + m] + t.y * cs3[NPT + m + 1] + t.z * cs3[NPT + m + 2] + t.w * cs3[NPT + m + 3];
            mz += t.x * cs3[2 * NPT + m] + t.y * cs3[2 * NPT + m + 1] + t.z * cs3[2 * NPT + m + 2] + t.w * cs3[2 * NPT + m + 3];
        }
        #pragma unroll
        for (int o = 16; o > 0; o >>= 1) {
            mx += __shfl_xor_sync(0xFFFFFFFFu, mx, o);
            my += __shfl_xor_sync(0xFFFFFFFFu, my, o);
            mz += __shfl_xor_sync(0xFFFFFFFFu, mz, o);
        }
        if (lane == 0) { wred3[warp][0] = mx; wred3[warp][1] = my; wred3[warp][2] = mz; }
        __syncthreads();
        if (tid == 0) {
            float sx = 0.f, sy = 0.f, sz = 0.f;
            #pragma unroll
            for (int w = 0; w < 8; w++) { sx += wred3[w][0]; sy += wred3[w][1]; sz += wred3[w][2]; }
            float rs = a_sh * kb_sh;
            float inv = 1.0f / (rs + 1e-8f);
            float* mout = out + (size_t)NB * NPT * NPT + ((size_t)b * NPT + n) * 3;
            mout[0] = sx * inv; mout[1] = sy * inv; mout[2] = sz * inv;
            g_rowsum[b * NPT + n] = rs;
        }
        __syncthreads();
    }
}

// -------- 6) weighted Kabsch per batch --------
__device__ __forceinline__ float block_reduce(float v, float* red) {
    int tid = threadIdx.x;
    red[tid] = v;
    __syncthreads();
    for (int o = 128; o > 0; o >>= 1) {
        if (tid < o) red[tid] += red[tid + o];
        __syncthreads();
    }
    float r = red[0];
    __syncthreads();
    return r;
}

__global__ __launch_bounds__(256) void rigid_kernel(const float* __restrict__ coords,
                                                    float* __restrict__ out) {
    __shared__ float red[256];
    int b = blockIdx.x, tid = threadIdx.x;
    const float* c1    = coords + (size_t)b * NPT * 4;
    const float* match = out + (size_t)NB * NPT * NPT + (size_t)b * NPT * 3;

    float s = 0.f;
    for (int i = 0; i < 16; i++) s += g_rowsum[b * NPT + tid + i * 256];
    float wsum  = block_reduce(s, red);
    float denom = wsum + 1e-5f;

    float pc[6] = {0, 0, 0, 0, 0, 0};
    for (int i = 0; i < 16; i++) {
        int n = tid + i * 256;
        float w = g_rowsum[b * NPT + n] / denom;
        pc[0] += w * c1[n * 4 + 1]; pc[1] += w * c1[n * 4 + 2]; pc[2] += w * c1[n * 4 + 3];
        pc[3] += w * match[n * 3 + 0]; pc[4] += w * match[n * 3 + 1]; pc[5] += w * match[n * 3 + 2];
    }
    float cent[6];
    for (int k = 0; k < 6; k++) cent[k] = block_reduce(pc[k], red);

    float pcv[9] = {0};
    for (int i = 0; i < 16; i++) {
        int n = tid + i * 256;
        float w  = g_rowsum[b * NPT + n] / denom;
        float ax = c1[n * 4 + 1] - cent[0], ay = c1[n * 4 + 2] - cent[1], az = c1[n * 4 + 3] - cent[2];
        float bx = (match[n * 3 + 0] - cent[3]) * w;
        float by = (match[n * 3 + 1] - cent[4]) * w;
        float bz = (match[n * 3 + 2] - cent[5]) * w;
        pcv[0] += ax * bx; pcv[1] += ax * by; pcv[2] += ax * bz;
        pcv[3] += ay * bx; pcv[4] += ay * by; pcv[5] += ay * bz;
        pcv[6] += az * bx; pcv[7] += az * by; pcv[8] += az * bz;
    }
    float cov[9];
    for (int k = 0; k < 9; k++) cov[k] = block_reduce(pcv[k], red);

    if (tid == 0) {
        double A[3][3];
        for (int r = 0; r < 3; r++)
            for (int c = 0; c < 3; c++) A[r][c] = (double)cov[r * 3 + c];
        double S[3][3];
        for (int r = 0; r < 3; r++)
            for (int c = 0; c < 3; c++)
                S[r][c] = A[0][r] * A[0][c] + A[1][r] * A[1][c] + A[2][r] * A[2][c];
        double V[3][3] = {{1, 0, 0}, {0, 1, 0}, {0, 0, 1}};
        const int PP[3] = {0, 0, 1}, QQ[3] = {1, 2, 2};
        for (int sweep = 0; sweep < 12; sweep++) {
            for (int pr = 0; pr < 3; pr++) {
                int p = PP[pr], q = QQ[pr];
                double apq = S[p][q];
                if (fabs(apq) < 1e-300) continue;
                double theta = (S[q][q] - S[p][p]) / (2.0 * apq);
                double t = ((theta >= 0.0) ? 1.0 : -1.0) / (fabs(theta) + sqrt(theta * theta + 1.0));
                double cth = 1.0 / sqrt(t * t + 1.0), sth = t * cth;
                for (int k = 0; k < 3; k++) {
                    double skp = S[k][p], skq = S[k][q];
                    S[k][p] = cth * skp - sth * skq;
                    S[k][q] = sth * skp + cth * skq;
                }
                for (int k = 0; k < 3; k++) {
                    double spk = S[p][k], sqk = S[q][k];
                    S[p][k] = cth * spk - sth * sqk;
                    S[q][k] = sth * spk + cth * sqk;
                }
                for (int k = 0; k < 3; k++) {
                    double vkp = V[k][p], vkq = V[k][q];
                    V[k][p] = cth * vkp - sth * vkq;
                    V[k][q] = sth * vkp + cth * vkq;
                }
            }
        }
        double ev[3] = {S[0][0], S[1][1], S[2][2]};
        int id[3] = {0, 1, 2};
        for (int i = 0; i < 2; i++)
            for (int j = 0; j < 2 - i; j++)
                if (ev[id[j]] < ev[id[j + 1]]) { int tmp = id[j]; id[j] = id[j + 1]; id[j + 1] = tmp; }
        double sv[3], Vs[3][3], U[3][3];
        for (int i = 0; i < 3; i++) {
            sv[i] = sqrt(fmax(ev[id[i]], 0.0));
            for (int r = 0; r < 3; r++) Vs[r][i] = V[r][id[i]];
        }
        for (int i = 0; i < 3; i++) {
            double inv = (sv[i] > 0.0) ? 1.0 / sv[i] : 0.0;
            for (int r = 0; r < 3; r++)
                U[r][i] = (A[r][0] * Vs[0][i] + A[r][1] * Vs[1][i] + A[r][2] * Vs[2][i]) * inv;
        }
        double detA = A[0][0] * (A[1][1] * A[2][2] - A[1][2] * A[2][1])
                    - A[0][1] * (A[1][0] * A[2][2] - A[1][2] * A[2][0])
                    + A[0][2] * (A[1][0] * A[2][1] - A[1][1] * A[2][0]);
        if (!(detA > 0.0)) { Vs[0][2] = -Vs[0][2]; Vs[1][2] = -Vs[1][2]; Vs[2][2] = -Vs[2][2]; }
        double R[3][3];
        for (int r = 0; r < 3; r++)
            for (int c = 0; c < 3; c++)
                R[r][c] = Vs[r][0] * U[c][0] + Vs[r][1] * U[c][1] + Vs[r][2] * U[c][2];
        float* tout = out + (size_t)NB * NPT * NPT + (size_t)NB * NPT * 3 + b * 12;
        for (int r = 0; r < 3; r++) {
            double tr = -(R[r][0] * cent[0] + R[r][1] * cent[1] + R[r][2] * cent[2]) + cent[3 + r];
            tout[r * 4 + 0] = (float)R[r][0];
            tout[r * 4 + 1] = (float)R[r][1];
            tout[r * 4 + 2] = (float)R[r][2];
            tout[r * 4 + 3] = (float)tr;
        }
    }
}

extern "C" void kernel_launch(void* const* d_in, const int* in_sizes, int n_in,
                              void* d_out, int out_size) {
    const float* pf     = (const float*)d_in[0];
    const float* coords = (const float*)d_in[1];
    const float* gamma  = (const float*)d_in[2];
    const float* epsv   = (const float*)d_in[3];
    float* out = (float*)d_out;

    cudaFuncSetAttribute(gemm_mma_kernel,
                         cudaFuncAttributeMaxDynamicSharedMemorySize, SMEM_DYN);
    cudaFuncSetAttribute(prep_kernel,
                         cudaFuncAttributeMaxDynamicSharedMemorySize, PRE_SMEM);
    cudaFuncSetAttribute(kb_final_kernel,
                         cudaFuncAttributeMaxDynamicSharedMemorySize, FIN_SMEM);

    prep_kernel<<<dim3(NPT / 32, 2 * NB), 256, PRE_SMEM>>>(pf);                   // 0
    gemm_mma_kernel<<<dim3(NPT / 128, NPT / 128, NB), 256, SMEM_DYN>>>(epsv);     // 1
    update_b_kernel<32><<<dim3(NPT / 256, NB), 256>>>(gamma, epsv);               // 2 -> b1
    for (int it = 0; it < 4; it++) {
        fused_kb_kta_kernel<<<dim3(NPT / 16, NB), 256>>>(gamma, epsv);            // 3 on it=0 (profiled)
        update_b_kernel<256><<<dim3(NPT / 256, NB), 256>>>(gamma, epsv);          // -> b2..b5
    }
    kb_final_kernel<<<dim3(NPT / 4, NB), 256, FIN_SMEM>>>(gamma, epsv, coords, out);
    rigid_kernel<<<NB, 256>>>(coords, out);
}

// round 16
// speedup vs baseline: 1.0178x; 1.0178x over previous
#include <cuda_runtime.h>
#include <cuda_bf16.h>
#include <cstdint>
#include <math.h>

#define NB   4      // batch pairs (B)
#define NPT  4096   // points per cloud (N)
#define CF   640    // feature dim (C)
#define INV_N (1.0f/4096.0f)

#define BKC  16
#define NKC  (CF/BKC)    // 40 k-chunks of 16
#define CSLOTS 256

// -------- scratch (device globals; no allocation allowed) --------
__device__ __nv_bfloat16 g_fhi[(size_t)2*NB*NPT*CF];  // bf16 hi part of normalized feats
__device__ __nv_bfloat16 g_flo[(size_t)2*NB*NPT*CF];  // bf16 lo residual
__device__ float g_K[(size_t)NB*NPT*NPT];              // exp kernel fp32, 256 MB
__device__ float g_cs[(size_t)NB*CSLOTS*NPT];          // KTa partials, 16 MB
__device__ float g_b[NB*NPT];
__device__ float g_rowsum[NB*NPT];

__device__ __forceinline__ uint32_t smem_u32(const void* p) {
    uint32_t a;
    asm("{ .reg .u64 t; cvta.to.shared.u64 t, %1; cvt.u32.u64 %0, t; }" : "=r"(a) : "l"(p));
    return a;
}

// -------- 1) fused prep: norm + transpose + bf16 hi/lo split --------
#define PRE_SMEM (32 * 641 * 4)
__global__ __launch_bounds__(256) void prep_kernel(const float* __restrict__ pf) {
    extern __shared__ float ps[];           // [32][641] padded
    __shared__ float partial[256];
    __shared__ float invs[32];
    int bb = blockIdx.y;
    int n0 = blockIdx.x * 32;
    int tid = threadIdx.x;
    int tx = tid & 31, ty = tid >> 5;
    float ss = 0.f;
    for (int c = ty; c < CF; c += 8) {
        float v = pf[((size_t)bb * CF + c) * NPT + n0 + tx];
        ps[tx * 641 + c] = v;
        ss += v * v;
    }
    partial[tid] = ss;
    __syncthreads();
    if (tid < 32) {
        float s = 0.f;
        #pragma unroll
        for (int g = 0; g < 8; g++) s += partial[g * 32 + tid];
        invs[tid] = 1.0f / sqrtf(s + 1e-8f);
    }
    __syncthreads();
    for (int idx = tid; idx < 32 * 320; idx += 256) {
        int n  = idx / 320;
        int cp = (idx - n * 320) * 2;
        float inv = invs[n];
        float v0 = ps[n * 641 + cp] * inv;
        float v1 = ps[n * 641 + cp + 1] * inv;
        __nv_bfloat16 h0 = __float2bfloat16(v0);
        __nv_bfloat16 h1 = __float2bfloat16(v1);
        float r0 = v0 - __bfloat162float(h0);
        float r1 = v1 - __bfloat162float(h1);
        size_t o = ((size_t)bb * NPT + n0 + n) * CF + cp;
        *(__nv_bfloat162*)(g_fhi + o) = __halves2bfloat162(h0, h1);
        *(__nv_bfloat162*)(g_flo + o) = __halves2bfloat162(__float2bfloat16(r0), __float2bfloat16(r1));
    }
}

// -------- 2) split-bf16 mma.sync GEMM + exp epilogue + KTa0 column sums --------
#define TILE_B   6144
#define STAGE_B  24576
#define NSTAGE   3
#define SMEM_DYN (NSTAGE * STAGE_B)
__global__ __launch_bounds__(256, 2) void gemm_mma_kernel(const float* __restrict__ eps_p) {
    extern __shared__ __align__(128) char sm[];
    int tid  = threadIdx.x;
    int wid  = tid >> 5, lane = tid & 31;
    int b    = blockIdx.z;
    int row0 = blockIdx.y * 128;
    int col0 = blockIdx.x * 128;
    size_t offA = (size_t)b * NPT * CF;
    size_t offB = (size_t)(b + NB) * NPT * CF;
    uint32_t sbase = smem_u32(sm);

    int lr = tid >> 1, lq = tid & 1;
    uint32_t rowoff = lr * 48 + lq * 16;
    auto load_stage = [&](int kc, int s) {
        uint32_t st = sbase + s * STAGE_B;
        size_t gA = offA + (size_t)(row0 + lr) * CF + kc * BKC + lq * 8;
        size_t gB = offB + (size_t)(col0 + lr) * CF + kc * BKC + lq * 8;
        asm volatile("cp.async.cg.shared.global [%0], [%1], 16;" :: "r"(st + rowoff),              "l"((const void*)(g_fhi + gA)));
        asm volatile("cp.async.cg.shared.global [%0], [%1], 16;" :: "r"(st + TILE_B + rowoff),     "l"((const void*)(g_flo + gA)));
        asm volatile("cp.async.cg.shared.global [%0], [%1], 16;" :: "r"(st + 2 * TILE_B + rowoff), "l"((const void*)(g_fhi + gB)));
        asm volatile("cp.async.cg.shared.global [%0], [%1], 16;" :: "r"(st + 3 * TILE_B + rowoff), "l"((const void*)(g_flo + gB)));
        asm volatile("cp.async.commit_group;" ::: "memory");
    };

    float acc[2][8][4];
    #pragma unroll
    for (int mt = 0; mt < 2; mt++)
        #pragma unroll
        for (int nt = 0; nt < 8; nt++)
            #pragma unroll
            for (int k = 0; k < 4; k++) acc[mt][nt][k] = 0.f;

    int warp_m = wid & 3, warp_n = wid >> 2;
    int p = lane >> 3, r8 = lane & 7;
    int arow = warp_m * 32 + (p & 1) * 8 + r8;
    int aq   = (p >> 1);
    int brow = warp_n * 64 + (p >> 1) * 8 + r8;
    int bq   = (p & 1);

    load_stage(0, 0);
    load_stage(1, 1);
    for (int kc = 0; kc < NKC; kc++) {
        if (kc + 1 < NKC) {
            asm volatile("cp.async.wait_group 1;" ::: "memory");
        } else {
            asm volatile("cp.async.wait_group 0;" ::: "memory");
        }
        __syncthreads();
        if (kc + 2 < NKC) load_stage(kc + 2, (kc + 2) % NSTAGE);
        uint32_t st = sbase + (kc % NSTAGE) * STAGE_B;

        uint32_t ah[2][4], al[2][4];
        #pragma unroll
        for (int mt = 0; mt < 2; mt++) {
            uint32_t ad = st + (arow + mt * 16) * 48 + aq * 16;
            asm volatile("ldmatrix.sync.aligned.m8n8.x4.shared.b16 {%0,%1,%2,%3}, [%4];"
                : "=r"(ah[mt][0]), "=r"(ah[mt][1]), "=r"(ah[mt][2]), "=r"(ah[mt][3]) : "r"(ad));
            asm volatile("ldmatrix.sync.aligned.m8n8.x4.shared.b16 {%0,%1,%2,%3}, [%4];"
                : "=r"(al[mt][0]), "=r"(al[mt][1]), "=r"(al[mt][2]), "=r"(al[mt][3]) : "r"(ad + TILE_B));
        }
        uint32_t bh[8][2], bl[8][2];
        #pragma unroll
        for (int np = 0; np < 4; np++) {
            uint32_t bd = st + 2 * TILE_B + (brow + np * 16) * 48 + bq * 16;
            uint32_t t0, t1, t2, t3;
            asm volatile("ldmatrix.sync.aligned.m8n8.x4.shared.b16 {%0,%1,%2,%3}, [%4];"
                : "=r"(t0), "=r"(t1), "=r"(t2), "=r"(t3) : "r"(bd));
            bh[2 * np][0] = t0; bh[2 * np][1] = t1;
            bh[2 * np + 1][0] = t2; bh[2 * np + 1][1] = t3;
            asm volatile("ldmatrix.sync.aligned.m8n8.x4.shared.b16 {%0,%1,%2,%3}, [%4];"
                : "=r"(t0), "=r"(t1), "=r"(t2), "=r"(t3) : "r"(bd + TILE_B));
            bl[2 * np][0] = t0; bl[2 * np][1] = t1;
            bl[2 * np + 1][0] = t2; bl[2 * np + 1][1] = t3;
        }
        #pragma unroll
        for (int mt = 0; mt < 2; mt++)
            #pragma unroll
            for (int nt = 0; nt < 8; nt++)
                asm volatile("mma.sync.aligned.m16n8k16.row.col.f32.bf16.bf16.f32 "
                    "{%0,%1,%2,%3}, {%4,%5,%6,%7}, {%8,%9}, {%0,%1,%2,%3};"
                    : "+f"(acc[mt][nt][0]), "+f"(acc[mt][nt][1]), "+f"(acc[mt][nt][2]), "+f"(acc[mt][nt][3])
                    : "r"(ah[mt][0]), "r"(ah[mt][1]), "r"(ah[mt][2]), "r"(ah[mt][3]),
                      "r"(bh[nt][0]), "r"(bh[nt][1]));
        #pragma unroll
        for (int mt = 0; mt < 2; mt++)
            #pragma unroll
            for (int nt = 0; nt < 8; nt++)
                asm volatile("mma.sync.aligned.m16n8k16.row.col.f32.bf16.bf16.f32 "
                    "{%0,%1,%2,%3}, {%4,%5,%6,%7}, {%8,%9}, {%0,%1,%2,%3};"
                    : "+f"(acc[mt][nt][0]), "+f"(acc[mt][nt][1]), "+f"(acc[mt][nt][2]), "+f"(acc[mt][nt][3])
                    : "r"(ah[mt][0]), "r"(ah[mt][1]), "r"(ah[mt][2]), "r"(ah[mt][3]),
                      "r"(bl[nt][0]), "r"(bl[nt][1]));
        #pragma unroll
        for (int mt = 0; mt < 2; mt++)
            #pragma unroll
            for (int nt = 0; nt < 8; nt++)
                asm volatile("mma.sync.aligned.m16n8k16.row.col.f32.bf16.bf16.f32 "
                    "{%0,%1,%2,%3}, {%4,%5,%6,%7}, {%8,%9}, {%0,%1,%2,%3};"
                    : "+f"(acc[mt][nt][0]), "+f"(acc[mt][nt][1]), "+f"(acc[mt][nt][2]), "+f"(acc[mt][nt][3])
                    : "r"(al[mt][0]), "r"(al[mt][1]), "r"(al[mt][2]), "r"(al[mt][3]),
                      "r"(bh[nt][0]), "r"(bh[nt][1]));
    }

    float eps = expf(eps_p[0]) + 0.03f;
    float inv_eps = 1.0f / eps;
    int gam = lane >> 2, lam = lane & 3;
    float csum[16];
    #pragma unroll
    for (int k = 0; k < 16; k++) csum[k] = 0.f;
    #pragma unroll
    for (int mt = 0; mt < 2; mt++) {
        #pragma unroll
        for (int half = 0; half < 2; half++) {
            int grow = row0 + warp_m * 32 + mt * 16 + half * 8 + gam;
            float* Kout = g_K + ((size_t)b * NPT + grow) * NPT + col0 + warp_n * 64;
            #pragma unroll
            for (int nt = 0; nt < 8; nt++) {
                float e0 = __expf((acc[mt][nt][2 * half + 0] - 1.0f) * inv_eps);
                float e1 = __expf((acc[mt][nt][2 * half + 1] - 1.0f) * inv_eps);
                *(float2*)(Kout + nt * 8 + lam * 2) = make_float2(e0, e1);
                csum[nt * 2 + 0] += e0;
                csum[nt * 2 + 1] += e1;
            }
        }
    }
    __syncthreads();
    float* colpart = (float*)sm;           // [256][17]
    #pragma unroll
    for (int k = 0; k < 16; k++) colpart[tid * 17 + k] = csum[k];
    __syncthreads();
    if (tid < 128) {
        int cc = tid;
        int wnc = cc >> 6;
        int rem = cc & 63;
        int ntc = rem >> 3;
        int lamc = (rem & 7) >> 1;
        int jc = rem & 1;
        float s = 0.f;
        #pragma unroll
        for (int wm = 0; wm < 4; wm++)
            #pragma unroll
            for (int gm = 0; gm < 8; gm++)
                s += colpart[((wnc * 4 + wm) * 32 + gm * 4 + lamc) * 17 + ntc * 2 + jc];
        g_cs[((size_t)b * CSLOTS + blockIdx.y) * NPT + col0 + cc] = s * INV_N;
    }
}

// -------- 3) update b from KTa partials (compile-time trip count) --------
template <int NP>
__global__ __launch_bounds__(256) void update_b_kernel(const float* __restrict__ gamma_p,
                                                       const float* __restrict__ eps_p) {
    int b = blockIdx.y;
    int m = blockIdx.x * 256 + threadIdx.x;
    const float* cs = g_cs + (size_t)b * CSLOTS * NPT + m;
    float s = 0.f;
    #pragma unroll
    for (int pp = 0; pp < NP; pp++) s += cs[(size_t)pp * NPT];
    float eps = expf(eps_p[0]) + 0.03f;
    float gam = expf(gamma_p[0]);
    float pw  = gam / (gam + eps);
    g_b[b * NPT + m] = powf(INV_N / (s + 1e-8f), pw);
}

// -------- 4) fused Kb -> a -> KTa partials (fp32 K, 16 rows/block) --------
// 4 groups of 4 rows; pass1: two warps per row (all 8 warps stream);
// pass2: re-read the 64KB-hot rows, accumulate a_n*K[n,:] into smem columns.
__global__ __launch_bounds__(256) void fused_kb_kta_kernel(const float* __restrict__ gamma_p,
                                                           const float* __restrict__ eps_p) {
    __shared__ float acc[4096];
    __shared__ float wred[8];
    __shared__ float a_sh[4];
    int b = blockIdx.y;
    int n0 = blockIdx.x * 16;
    int tid = threadIdx.x;
    int warp = tid >> 5, lane = tid & 31;
    const float* bv = g_b + b * NPT;
    float eps = expf(eps_p[0]) + 0.03f;
    float gmv = expf(gamma_p[0]);
    float pw  = gmv / (gmv + eps);

    #pragma unroll
    for (int i = 0; i < 16; i++) acc[tid + i * 256] = 0.f;
    __syncthreads();

    for (int g = 0; g < 4; g++) {
        {
            int n = n0 + g * 4 + (warp >> 1);
            int half = warp & 1;
            const float* Krow = g_K + ((size_t)b * NPT + n) * NPT + half * 2048;
            const float* bvh  = bv + half * 2048;
            float s = 0.f;
            #pragma unroll
            for (int j = 0; j < 16; j++) {
                int m = (j * 32 + lane) * 4;
                float4 k4 = *(const float4*)(Krow + m);
                float4 b4 = *(const float4*)(bvh + m);
                s += k4.x * b4.x + k4.y * b4.y + k4.z * b4.z + k4.w * b4.w;
            }
            #pragma unroll
            for (int o = 16; o > 0; o >>= 1) s += __shfl_xor_sync(0xFFFFFFFFu, s, o);
            if (lane == 0) wred[warp] = s;
        }
        __syncthreads();
        if (tid < 4) {
            float kb = wred[2 * tid] + wred[2 * tid + 1];
            a_sh[tid] = powf(INV_N / (kb + 1e-8f), pw);
        }
        __syncthreads();
        #pragma unroll
        for (int r = 0; r < 4; r++) {
            int n = n0 + g * 4 + r;
            float an = a_sh[r];
            const float* Krow = g_K + ((size_t)b * NPT + n) * NPT;
            #pragma unroll
            for (int j = 0; j < 4; j++) {
                int c = warp * 512 + j * 128 + lane * 4;
                float4 k4 = *(const float4*)(Krow + c);
                float4 av = *(float4*)(acc + c);
                av.x += an * k4.x; av.y += an * k4.y;
                av.z += an * k4.z; av.w += an * k4.w;
                *(float4*)(acc + c) = av;
            }
        }
        __syncthreads();
    }
    float* dst = g_cs + ((size_t)b * CSLOTS + blockIdx.x) * NPT;
    #pragma unroll
    for (int i = 0; i < 16; i++) dst[tid + i * 256] = acc[tid + i * 256];
}

// -------- 5) fused: last Kb + a-update + T + row_sum + matches --------
#define FIN_SMEM (3 * NPT * 4)
__global__ __launch_bounds__(256) void kb_final_kernel(const float* __restrict__ gamma_p,
                                                       const float* __restrict__ eps_p,
                                                       const float* __restrict__ coords,
                                                       float* __restrict__ out) {
    extern __shared__ float cs3[];           // [3][NPT]: y, z, w
    __shared__ float wred[8];
    __shared__ float wred3[8][3];
    __shared__ float a_sh, kb_sh;
    int b = blockIdx.y;
    int tid = threadIdx.x;
    int warp = tid >> 5, lane = tid & 31;
    const float* bv = g_b + b * NPT;
    const float* c2 = coords + (size_t)(NB + b) * NPT * 4;

    for (int idx = tid; idx < NPT; idx += 256) {
        float4 cc = *(const float4*)(c2 + (size_t)idx * 4);
        cs3[idx] = cc.y;
        cs3[NPT + idx] = cc.z;
        cs3[2 * NPT + idx] = cc.w;
    }
    float4 br[4];
    #pragma unroll
    for (int i = 0; i < 4; i++) br[i] = *(const float4*)(bv + tid * 4 + i * 1024);
    __syncthreads();

    float eps = expf(eps_p[0]) + 0.03f;
    float gmv = expf(gamma_p[0]);
    float pw  = gmv / (gmv + eps);

    for (int r = 0; r < 4; r++) {
        int n = blockIdx.x * 4 + r;
        const float* Krow = g_K + ((size_t)b * NPT + n) * NPT;
        float4 kr[4];
        float s = 0.f;
        #pragma unroll
        for (int i = 0; i < 4; i++) {
            int m = tid * 4 + i * 1024;
            kr[i] = __ldcs((const float4*)(Krow + m));
            s += kr[i].x * br[i].x + kr[i].y * br[i].y + kr[i].z * br[i].z + kr[i].w * br[i].w;
        }
        #pragma unroll
        for (int o = 16; o > 0; o >>= 1) s += __shfl_xor_sync(0xFFFFFFFFu, s, o);
        if (lane == 0) wred[warp] = s;
        __syncthreads();
        if (tid == 0) {
            float kb = 0.f;
            #pragma unroll
            for (int w = 0; w < 8; w++) kb += wred[w];
            kb_sh = kb;
            a_sh  = powf(INV_N / (kb + 1e-8f), pw);
        }
        __syncthreads();
        float a = a_sh;
        float* Trow = out + ((size_t)b * NPT + n) * NPT;
        float mx = 0.f, my = 0.f, mz = 0.f;
        #pragma unroll
        for (int i = 0; i < 4; i++) {
            int m = tid * 4 + i * 1024;
            float4 t;
            t.x = a * kr[i].x * br[i].x;
            t.y = a * kr[i].y * br[i].y;
            t.z = a * kr[i].z * br[i].z;
            t.w = a * kr[i].w * br[i].w;
            __stcs((float4*)(Trow + m), t);
            mx += t.x * cs3[m] + t.y * cs3[m + 1] + t.z * cs3[m + 2] + t.w * cs3[m + 3];
            my += t.x * cs3[NPT + m] + t.y * cs3[NPT + m + 1] + t.z * cs3[NPT + m + 2] + t.w * cs3[NPT + m + 3];
            mz += t.x * cs3[2 * NPT + m] + t.y * cs3[2 * NPT + m + 1] + t.z * cs3[2 * NPT + m + 2] + t.w * cs3[2 * NPT + m + 3];
        }
        #pragma unroll
        for (int o = 16; o > 0; o >>= 1) {
            mx += __shfl_xor_sync(0xFFFFFFFFu, mx, o);
            my += __shfl_xor_sync(0xFFFFFFFFu, my, o);
            mz += __shfl_xor_sync(0xFFFFFFFFu, mz, o);
        }
        if (lane == 0) { wred3[warp][0] = mx; wred3[warp][1] = my; wred3[warp][2] = mz; }
        __syncthreads();
        if (tid == 0) {
            float sx = 0.f, sy = 0.f, sz = 0.f;
            #pragma unroll
            for (int w = 0; w < 8; w++) { sx += wred3[w][0]; sy += wred3[w][1]; sz += wred3[w][2]; }
            float rs = a_sh * kb_sh;
            float inv = 1.0f / (rs + 1e-8f);
            float* mout = out + (size_t)NB * NPT * NPT + ((size_t)b * NPT + n) * 3;
            mout[0] = sx * inv; mout[1] = sy * inv; mout[2] = sz * inv;
            g_rowsum[b * NPT + n] = rs;
        }
        __syncthreads();
    }
}

// -------- 6) weighted Kabsch per batch --------
__device__ __forceinline__ float block_reduce(float v, float* red) {
    int tid = threadIdx.x;
    red[tid] = v;
    __syncthreads();
    for (int o = 128; o > 0; o >>= 1) {
        if (tid < o) red[tid] += red[tid + o];
        __syncthreads();
    }
    float r = red[0];
    __syncthreads();
    return r;
}

__global__ __launch_bounds__(256) void rigid_kernel(const float* __restrict__ coords,
                                                    float* __restrict__ out) {
    __shared__ float red[256];
    int b = blockIdx.x, tid = threadIdx.x;
    const float* c1    = coords + (size_t)b * NPT * 4;
    const float* match = out + (size_t)NB * NPT * NPT + (size_t)b * NPT * 3;

    float s = 0.f;
    for (int i = 0; i < 16; i++) s += g_rowsum[b * NPT + tid + i * 256];
    float wsum  = block_reduce(s, red);
    float denom = wsum + 1e-5f;

    float pc[6] = {0, 0, 0, 0, 0, 0};
    for (int i = 0; i < 16; i++) {
        int n = tid + i * 256;
        float w = g_rowsum[b * NPT + n] / denom;
        pc[0] += w * c1[n * 4 + 1]; pc[1] += w * c1[n * 4 + 2]; pc[2] += w * c1[n * 4 + 3];
        pc[3] += w * match[n * 3 + 0]; pc[4] += w * match[n * 3 + 1]; pc[5] += w * match[n * 3 + 2];
    }
    float cent[6];
    for (int k = 0; k < 6; k++) cent[k] = block_reduce(pc[k], red);

    float pcv[9] = {0};
    for (int i = 0; i < 16; i++) {
        int n = tid + i * 256;
        float w  = g_rowsum[b * NPT + n] / denom;
        float ax = c1[n * 4 + 1] - cent[0], ay = c1[n * 4 + 2] - cent[1], az = c1[n * 4 + 3] - cent[2];
        float bx = (match[n * 3 + 0] - cent[3]) * w;
        float by = (match[n * 3 + 1] - cent[4]) * w;
        float bz = (match[n * 3 + 2] - cent[5]) * w;
        pcv[0] += ax * bx; pcv[1] += ax * by; pcv[2] += ax * bz;
        pcv[3] += ay * bx; pcv[4] += ay * by; pcv[5] += ay * bz;
        pcv[6] += az * bx; pcv[7] += az * by; pcv[8] += az * bz;
    }
    float cov[9];
    for (int k = 0; k < 9; k++) cov[k] = block_reduce(pcv[k], red);

    if (tid == 0) {
        double A[3][3];
        for (int r = 0; r < 3; r++)
            for (int c = 0; c < 3; c++) A[r][c] = (double)cov[r * 3 + c];
        double S[3][3];
        for (int r = 0; r < 3; r++)
            for (int c = 0; c < 3; c++)
                S[r][c] = A[0][r] * A[0][c] + A[1][r] * A[1][c] + A[2][r] * A[2][c];
        double V[3][3] = {{1, 0, 0}, {0, 1, 0}, {0, 0, 1}};
        const int PP[3] = {0, 0, 1}, QQ[3] = {1, 2, 2};
        for (int sweep = 0; sweep < 12; sweep++) {
            for (int pr = 0; pr < 3; pr++) {
                int p = PP[pr], q = QQ[pr];
                double apq = S[p][q];
                if (fabs(apq) < 1e-300) continue;
                double theta = (S[q][q] - S[p][p]) / (2.0 * apq);
                double t = ((theta >= 0.0) ? 1.0 : -1.0) / (fabs(theta) + sqrt(theta * theta + 1.0));
                double cth = 1.0 / sqrt(t * t + 1.0), sth = t * cth;
                for (int k = 0; k < 3; k++) {
                    double skp = S[k][p], skq = S[k][q];
                    S[k][p] = cth * skp - sth * skq;
                    S[k][q] = sth * skp + cth * skq;
                }
                for (int k = 0; k < 3; k++) {
                    double spk = S[p][k], sqk = S[q][k];
                    S[p][k] = cth * spk - sth * sqk;
                    S[q][k] = sth * spk + cth * sqk;
                }
                for (int k = 0; k < 3; k++) {
                    double vkp = V[k][p], vkq = V[k][q];
                    V[k][p] = cth * vkp - sth * vkq;
                    V[k][q] = sth * vkp + cth * vkq;
                }
            }
        }
        double ev[3] = {S[0][0], S[1][1], S[2][2]};
        int id[3] = {0, 1, 2};
        for (int i = 0; i < 2; i++)
            for (int j = 0; j < 2 - i; j++)
                if (ev[id[j]] < ev[id[j + 1]]) { int tmp = id[j]; id[j] = id[j + 1]; id[j + 1] = tmp; }
        double sv[3], Vs[3][3], U[3][3];
        for (int i = 0; i < 3; i++) {
            sv[i] = sqrt(fmax(ev[id[i]], 0.0));
            for (int r = 0; r < 3; r++) Vs[r][i] = V[r][id[i]];
        }
        for (int i = 0; i < 3; i++) {
            double inv = (sv[i] > 0.0) ? 1.0 / sv[i] : 0.0;
            for (int r = 0; r < 3; r++)
                U[r][i] = (A[r][0] * Vs[0][i] + A[r][1] * Vs[1][i] + A[r][2] * Vs[2][i]) * inv;
        }
        double detA = A[0][0] * (A[1][1] * A[2][2] - A[1][2] * A[2][1])
                    - A[0][1] * (A[1][0] * A[2][2] - A[1][2] * A[2][0])
                    + A[0][2] * (A[1][0] * A[2][1] - A[1][1] * A[2][0]);
        if (!(detA > 0.0)) { Vs[0][2] = -Vs[0][2]; Vs[1][2] = -Vs[1][2]; Vs[2][2] = -Vs[2][2]; }
        double R[3][3];
        for (int r = 0; r < 3; r++)
            for (int c = 0; c < 3; c++)
                R[r][c] = Vs[r][0] * U[c][0] + Vs[r][1] * U[c][1] + Vs[r][2] * U[c][2];
        float* tout = out + (size_t)NB * NPT * NPT + (size_t)NB * NPT * 3 + b * 12;
        for (int r = 0; r < 3; r++) {
            double tr = -(R[r][0] * cent[0] + R[r][1] * cent[1] + R[r][2] * cent[2]) + cent[3 + r];
            tout[r * 4 + 0] = (float)R[r][0];
            tout[r * 4 + 1] = (float)R[r][1];
            tout[r * 4 + 2] = (float)R[r][2];
            tout[r * 4 + 3] = (float)tr;
        }
    }
}

extern "C" void kernel_launch(void* const* d_in, const int* in_sizes, int n_in,
                              void* d_out, int out_size) {
    const float* pf     = (const float*)d_in[0];
    const float* coords = (const float*)d_in[1];
    const float* gamma  = (const float*)d_in[2];
    const float* epsv   = (const float*)d_in[3];
    float* out = (float*)d_out;

    cudaFuncSetAttribute(gemm_mma_kernel,
                         cudaFuncAttributeMaxDynamicSharedMemorySize, SMEM_DYN);
    cudaFuncSetAttribute(prep_kernel,
                         cudaFuncAttributeMaxDynamicSharedMemorySize, PRE_SMEM);
    cudaFuncSetAttribute(kb_final_kernel,
                         cudaFuncAttributeMaxDynamicSharedMemorySize, FIN_SMEM);

    prep_kernel<<<dim3(NPT / 32, 2 * NB), 256, PRE_SMEM>>>(pf);                   // 0
    gemm_mma_kernel<<<dim3(NPT / 128, NPT / 128, NB), 256, SMEM_DYN>>>(epsv);     // 1
    update_b_kernel<32><<<dim3(NPT / 256, NB), 256>>>(gamma, epsv);               // 2 -> b1
    for (int it = 0; it < 4; it++) {
        fused_kb_kta_kernel<<<dim3(NPT / 16, NB), 256>>>(gamma, epsv);            // 3 on it=0 (profiled)
        update_b_kernel<256><<<dim3(NPT / 256, NB), 256>>>(gamma, epsv);          // -> b2..b5
    }
    kb_final_kernel<<<dim3(NPT / 4, NB), 256, FIN_SMEM>>>(gamma, epsv, coords, out);
    rigid_kernel<<<NB, 256>>>(coords, out);
}

// round 17
// speedup vs baseline: 1.0581x; 1.0396x over previous
#include <cuda_runtime.h>
#include <cuda_bf16.h>
#include <cstdint>
#include <math.h>

#define NB   4      // batch pairs (B)
#define NPT  4096   // points per cloud (N)
#define CF   640    // feature dim (C)
#define INV_N (1.0f/4096.0f)

#define BKC  16
#define NKC  (CF/BKC)    // 40 k-chunks of 16

// -------- scratch (device globals; no allocation allowed) --------
__device__ __nv_bfloat16 g_fhi[(size_t)2*NB*NPT*CF];  // bf16 hi part of normalized feats
__device__ __nv_bfloat16 g_flo[(size_t)2*NB*NPT*CF];  // bf16 lo residual
__device__ float g_K[(size_t)NB*NPT*NPT];              // exp kernel fp32, 256 MB
__device__ float g_cs[(size_t)NB*128*NPT];             // KTa partials, 8 MB
__device__ float g_b[NB*NPT];
__device__ float g_rowsum[NB*NPT];

__device__ __forceinline__ uint32_t smem_u32(const void* p) {
    uint32_t a;
    asm("{ .reg .u64 t; cvta.to.shared.u64 t, %1; cvt.u32.u64 %0, t; }" : "=r"(a) : "l"(p));
    return a;
}

// -------- 1) fused prep: norm + transpose + bf16 hi/lo split --------
#define PRE_SMEM (32 * 641 * 4)
__global__ __launch_bounds__(256) void prep_kernel(const float* __restrict__ pf) {
    extern __shared__ float ps[];           // [32][641] padded
    __shared__ float partial[256];
    __shared__ float invs[32];
    int bb = blockIdx.y;
    int n0 = blockIdx.x * 32;
    int tid = threadIdx.x;
    int tx = tid & 31, ty = tid >> 5;
    float ss = 0.f;
    for (int c = ty; c < CF; c += 8) {
        float v = pf[((size_t)bb * CF + c) * NPT + n0 + tx];
        ps[tx * 641 + c] = v;
        ss += v * v;
    }
    partial[tid] = ss;
    __syncthreads();
    if (tid < 32) {
        float s = 0.f;
        #pragma unroll
        for (int g = 0; g < 8; g++) s += partial[g * 32 + tid];
        invs[tid] = 1.0f / sqrtf(s + 1e-8f);
    }
    __syncthreads();
    for (int idx = tid; idx < 32 * 320; idx += 256) {
        int n  = idx / 320;
        int cp = (idx - n * 320) * 2;
        float inv = invs[n];
        float v0 = ps[n * 641 + cp] * inv;
        float v1 = ps[n * 641 + cp + 1] * inv;
        __nv_bfloat16 h0 = __float2bfloat16(v0);
        __nv_bfloat16 h1 = __float2bfloat16(v1);
        float r0 = v0 - __bfloat162float(h0);
        float r1 = v1 - __bfloat162float(h1);
        size_t o = ((size_t)bb * NPT + n0 + n) * CF + cp;
        *(__nv_bfloat162*)(g_fhi + o) = __halves2bfloat162(h0, h1);
        *(__nv_bfloat162*)(g_flo + o) = __halves2bfloat162(__float2bfloat16(r0), __float2bfloat16(r1));
    }
}

// -------- 2) split-bf16 mma.sync GEMM + exp epilogue + KTa0 column sums --------
#define TILE_B   6144
#define STAGE_B  24576
#define NSTAGE   3
#define SMEM_DYN (NSTAGE * STAGE_B)
__global__ __launch_bounds__(256, 2) void gemm_mma_kernel(const float* __restrict__ eps_p) {
    extern __shared__ __align__(128) char sm[];
    int tid  = threadIdx.x;
    int wid  = tid >> 5, lane = tid & 31;
    int b    = blockIdx.z;
    int row0 = blockIdx.y * 128;
    int col0 = blockIdx.x * 128;
    size_t offA = (size_t)b * NPT * CF;
    size_t offB = (size_t)(b + NB) * NPT * CF;
    uint32_t sbase = smem_u32(sm);

    int lr = tid >> 1, lq = tid & 1;
    uint32_t rowoff = lr * 48 + lq * 16;
    auto load_stage = [&](int kc, int s) {
        uint32_t st = sbase + s * STAGE_B;
        size_t gA = offA + (size_t)(row0 + lr) * CF + kc * BKC + lq * 8;
        size_t gB = offB + (size_t)(col0 + lr) * CF + kc * BKC + lq * 8;
        asm volatile("cp.async.cg.shared.global [%0], [%1], 16;" :: "r"(st + rowoff),              "l"((const void*)(g_fhi + gA)));
        asm volatile("cp.async.cg.shared.global [%0], [%1], 16;" :: "r"(st + TILE_B + rowoff),     "l"((const void*)(g_flo + gA)));
        asm volatile("cp.async.cg.shared.global [%0], [%1], 16;" :: "r"(st + 2 * TILE_B + rowoff), "l"((const void*)(g_fhi + gB)));
        asm volatile("cp.async.cg.shared.global [%0], [%1], 16;" :: "r"(st + 3 * TILE_B + rowoff), "l"((const void*)(g_flo + gB)));
        asm volatile("cp.async.commit_group;" ::: "memory");
    };

    float acc[2][8][4];
    #pragma unroll
    for (int mt = 0; mt < 2; mt++)
        #pragma unroll
        for (int nt = 0; nt < 8; nt++)
            #pragma unroll
            for (int k = 0; k < 4; k++) acc[mt][nt][k] = 0.f;

    int warp_m = wid & 3, warp_n = wid >> 2;
    int p = lane >> 3, r8 = lane & 7;
    int arow = warp_m * 32 + (p & 1) * 8 + r8;
    int aq   = (p >> 1);
    int brow = warp_n * 64 + (p >> 1) * 8 + r8;
    int bq   = (p & 1);

    load_stage(0, 0);
    load_stage(1, 1);
    for (int kc = 0; kc < NKC; kc++) {
        if (kc + 1 < NKC) {
            asm volatile("cp.async.wait_group 1;" ::: "memory");
        } else {
            asm volatile("cp.async.wait_group 0;" ::: "memory");
        }
        __syncthreads();
        if (kc + 2 < NKC) load_stage(kc + 2, (kc + 2) % NSTAGE);
        uint32_t st = sbase + (kc % NSTAGE) * STAGE_B;

        uint32_t ah[2][4], al[2][4];
        #pragma unroll
        for (int mt = 0; mt < 2; mt++) {
            uint32_t ad = st + (arow + mt * 16) * 48 + aq * 16;
            asm volatile("ldmatrix.sync.aligned.m8n8.x4.shared.b16 {%0,%1,%2,%3}, [%4];"
                : "=r"(ah[mt][0]), "=r"(ah[mt][1]), "=r"(ah[mt][2]), "=r"(ah[mt][3]) : "r"(ad));
            asm volatile("ldmatrix.sync.aligned.m8n8.x4.shared.b16 {%0,%1,%2,%3}, [%4];"
                : "=r"(al[mt][0]), "=r"(al[mt][1]), "=r"(al[mt][2]), "=r"(al[mt][3]) : "r"(ad + TILE_B));
        }
        uint32_t bh[8][2], bl[8][2];
        #pragma unroll
        for (int np = 0; np < 4; np++) {
            uint32_t bd = st + 2 * TILE_B + (brow + np * 16) * 48 + bq * 16;
            uint32_t t0, t1, t2, t3;
            asm volatile("ldmatrix.sync.aligned.m8n8.x4.shared.b16 {%0,%1,%2,%3}, [%4];"
                : "=r"(t0), "=r"(t1), "=r"(t2), "=r"(t3) : "r"(bd));
            bh[2 * np][0] = t0; bh[2 * np][1] = t1;
            bh[2 * np + 1][0] = t2; bh[2 * np + 1][1] = t3;
            asm volatile("ldmatrix.sync.aligned.m8n8.x4.shared.b16 {%0,%1,%2,%3}, [%4];"
                : "=r"(t0), "=r"(t1), "=r"(t2), "=r"(t3) : "r"(bd + TILE_B));
            bl[2 * np][0] = t0; bl[2 * np][1] = t1;
            bl[2 * np + 1][0] = t2; bl[2 * np + 1][1] = t3;
        }
        #pragma unroll
        for (int mt = 0; mt < 2; mt++)
            #pragma unroll
            for (int nt = 0; nt < 8; nt++)
                asm volatile("mma.sync.aligned.m16n8k16.row.col.f32.bf16.bf16.f32 "
                    "{%0,%1,%2,%3}, {%4,%5,%6,%7}, {%8,%9}, {%0,%1,%2,%3};"
                    : "+f"(acc[mt][nt][0]), "+f"(acc[mt][nt][1]), "+f"(acc[mt][nt][2]), "+f"(acc[mt][nt][3])
                    : "r"(ah[mt][0]), "r"(ah[mt][1]), "r"(ah[mt][2]), "r"(ah[mt][3]),
                      "r"(bh[nt][0]), "r"(bh[nt][1]));
        #pragma unroll
        for (int mt = 0; mt < 2; mt++)
            #pragma unroll
            for (int nt = 0; nt < 8; nt++)
                asm volatile("mma.sync.aligned.m16n8k16.row.col.f32.bf16.bf16.f32 "
                    "{%0,%1,%2,%3}, {%4,%5,%6,%7}, {%8,%9}, {%0,%1,%2,%3};"
                    : "+f"(acc[mt][nt][0]), "+f"(acc[mt][nt][1]), "+f"(acc[mt][nt][2]), "+f"(acc[mt][nt][3])
                    : "r"(ah[mt][0]), "r"(ah[mt][1]), "r"(ah[mt][2]), "r"(ah[mt][3]),
                      "r"(bl[nt][0]), "r"(bl[nt][1]));
        #pragma unroll
        for (int mt = 0; mt < 2; mt++)
            #pragma unroll
            for (int nt = 0; nt < 8; nt++)
                asm volatile("mma.sync.aligned.m16n8k16.row.col.f32.bf16.bf16.f32 "
                    "{%0,%1,%2,%3}, {%4,%5,%6,%7}, {%8,%9}, {%0,%1,%2,%3};"
                    : "+f"(acc[mt][nt][0]), "+f"(acc[mt][nt][1]), "+f"(acc[mt][nt][2]), "+f"(acc[mt][nt][3])
                    : "r"(al[mt][0]), "r"(al[mt][1]), "r"(al[mt][2]), "r"(al[mt][3]),
                      "r"(bh[nt][0]), "r"(bh[nt][1]));
    }

    float eps = expf(eps_p[0]) + 0.03f;
    float inv_eps = 1.0f / eps;
    int gam = lane >> 2, lam = lane & 3;
    float csum[16];
    #pragma unroll
    for (int k = 0; k < 16; k++) csum[k] = 0.f;
    #pragma unroll
    for (int mt = 0; mt < 2; mt++) {
        #pragma unroll
        for (int half = 0; half < 2; half++) {
            int grow = row0 + warp_m * 32 + mt * 16 + half * 8 + gam;
            float* Kout = g_K + ((size_t)b * NPT + grow) * NPT + col0 + warp_n * 64;
            #pragma unroll
            for (int nt = 0; nt < 8; nt++) {
                float e0 = __expf((acc[mt][nt][2 * half + 0] - 1.0f) * inv_eps);
                float e1 = __expf((acc[mt][nt][2 * half + 1] - 1.0f) * inv_eps);
                *(float2*)(Kout + nt * 8 + lam * 2) = make_float2(e0, e1);
                csum[nt * 2 + 0] += e0;
                csum[nt * 2 + 1] += e1;
            }
        }
    }
    __syncthreads();
    float* colpart = (float*)sm;           // [256][17]
    #pragma unroll
    for (int k = 0; k < 16; k++) colpart[tid * 17 + k] = csum[k];
    __syncthreads();
    if (tid < 128) {
        int cc = tid;
        int wnc = cc >> 6;
        int rem = cc & 63;
        int ntc = rem >> 3;
        int lamc = (rem & 7) >> 1;
        int jc = rem & 1;
        float s = 0.f;
        #pragma unroll
        for (int wm = 0; wm < 4; wm++)
            #pragma unroll
            for (int gm = 0; gm < 8; gm++)
                s += colpart[((wnc * 4 + wm) * 32 + gm * 4 + lamc) * 17 + ntc * 2 + jc];
        g_cs[((size_t)b * 128 + blockIdx.y) * NPT + col0 + cc] = s * INV_N;
    }
}

// -------- 3) update b from KTa partials (compile-time trip count) --------
template <int NP>
__global__ __launch_bounds__(256) void update_b_kernel(const float* __restrict__ gamma_p,
                                                       const float* __restrict__ eps_p) {
    int b = blockIdx.y;
    int m = blockIdx.x * 256 + threadIdx.x;
    const float* cs = g_cs + (size_t)b * 128 * NPT + m;
    float s = 0.f;
    #pragma unroll
    for (int pp = 0; pp < NP; pp++) s += cs[(size_t)pp * NPT];
    float eps = expf(eps_p[0]) + 0.03f;
    float gam = expf(gamma_p[0]);
    float pw  = gam / (gam + eps);
    g_b[b * NPT + m] = powf(INV_N / (s + 1e-8f), pw);
}

// -------- 4) fused Kb -> a -> KTa partials: SINGLE K pass, register-resident --------
// 16 groups of 2 rows; 4 warps per row, each warp a quarter-row; K values held in
// registers through the a-broadcast, then scaled into a persistent register acc.
// 2-phase smem merge at the end (deterministic, conflict-free).
__global__ __launch_bounds__(256, 2) void fused_kb_kta_kernel(const float* __restrict__ gamma_p,
                                                              const float* __restrict__ eps_p) {
    __shared__ float bsh[4096];      // b staged; reused as merge buffer after the loop
    __shared__ float wred[8];
    __shared__ float a_sh[2];
    int b = blockIdx.y;
    int n0 = blockIdx.x * 32;
    int tid = threadIdx.x;
    int warp = tid >> 5, lane = tid & 31;
    int rig = warp >> 2;             // row in group: 0/1
    int quarter = warp & 3;          // quarter-row
    const float* bv = g_b + b * NPT;
    float eps = expf(eps_p[0]) + 0.03f;
    float gmv = expf(gamma_p[0]);
    float pw  = gmv / (gmv + eps);

    for (int idx = tid; idx < 4096; idx += 256) bsh[idx] = bv[idx];

    float4 accr[8];
    #pragma unroll
    for (int j = 0; j < 8; j++) accr[j] = make_float4(0.f, 0.f, 0.f, 0.f);
    __syncthreads();

    int qoff = quarter * 1024;
    for (int g = 0; g < 16; g++) {
        int n = n0 + g * 2 + rig;
        const float* Krow = g_K + ((size_t)b * NPT + n) * NPT + qoff;
        float4 kr[8];
        float s = 0.f;
        #pragma unroll
        for (int j = 0; j < 8; j++) {
            int m = (j * 32 + lane) * 4;
            kr[j] = __ldcs((const float4*)(Krow + m));
            float4 b4 = *(const float4*)(bsh + qoff + m);
            s += kr[j].x * b4.x + kr[j].y * b4.y + kr[j].z * b4.z + kr[j].w * b4.w;
        }
        #pragma unroll
        for (int o = 16; o > 0; o >>= 1) s += __shfl_xor_sync(0xFFFFFFFFu, s, o);
        if (lane == 0) wred[warp] = s;
        __syncthreads();
        if (tid < 2) {
            float kb = wred[4 * tid] + wred[4 * tid + 1] + wred[4 * tid + 2] + wred[4 * tid + 3];
            a_sh[tid] = powf(INV_N / (kb + 1e-8f), pw);
        }
        __syncthreads();
        float an = a_sh[rig];
        #pragma unroll
        for (int j = 0; j < 8; j++) {
            accr[j].x += an * kr[j].x;
            accr[j].y += an * kr[j].y;
            accr[j].z += an * kr[j].z;
            accr[j].w += an * kr[j].w;
        }
    }

    // merge the two row-sets (warps q and q+4 share columns) through bsh
    __syncthreads();
    if (rig == 0) {
        #pragma unroll
        for (int j = 0; j < 8; j++)
            *(float4*)(bsh + qoff + (j * 32 + lane) * 4) = accr[j];
    }
    __syncthreads();
    if (rig == 1) {
        #pragma unroll
        for (int j = 0; j < 8; j++) {
            float* p = bsh + qoff + (j * 32 + lane) * 4;
            float4 v = *(float4*)p;
            v.x += accr[j].x; v.y += accr[j].y; v.z += accr[j].z; v.w += accr[j].w;
            *(float4*)p = v;
        }
    }
    __syncthreads();
    float* dst = g_cs + ((size_t)b * 128 + blockIdx.x) * NPT;
    #pragma unroll
    for (int i = 0; i < 16; i++) dst[tid + i * 256] = bsh[tid + i * 256];
}

// -------- 5) fused: last Kb + a-update + T + row_sum + matches --------
#define FIN_SMEM (3 * NPT * 4)
__global__ __launch_bounds__(256) void kb_final_kernel(const float* __restrict__ gamma_p,
                                                       const float* __restrict__ eps_p,
                                                       const float* __restrict__ coords,
                                                       float* __restrict__ out) {
    extern __shared__ float cs3[];           // [3][NPT]: y, z, w
    __shared__ float wred[8];
    __shared__ float wred3[8][3];
    __shared__ float a_sh, kb_sh;
    int b = blockIdx.y;
    int tid = threadIdx.x;
    int warp = tid >> 5, lane = tid & 31;
    const float* bv = g_b + b * NPT;
    const float* c2 = coords + (size_t)(NB + b) * NPT * 4;

    for (int idx = tid; idx < NPT; idx += 256) {
        float4 cc = *(const float4*)(c2 + (size_t)idx * 4);
        cs3[idx] = cc.y;
        cs3[NPT + idx] = cc.z;
        cs3[2 * NPT + idx] = cc.w;
    }
    float4 br[4];
    #pragma unroll
    for (int i = 0; i < 4; i++) br[i] = *(const float4*)(bv + tid * 4 + i * 1024);
    __syncthreads();

    float eps = expf(eps_p[0]) + 0.03f;
    float gmv = expf(gamma_p[0]);
    float pw  = gmv / (gmv + eps);

    for (int r = 0; r < 4; r++) {
        int n = blockIdx.x * 4 + r;
        const float* Krow = g_K + ((size_t)b * NPT + n) * NPT;
        float4 kr[4];
        float s = 0.f;
        #pragma unroll
        for (int i = 0; i < 4; i++) {
            int m = tid * 4 + i * 1024;
            kr[i] = __ldcs((const float4*)(Krow + m));
            s += kr[i].x * br[i].x + kr[i].y * br[i].y + kr[i].z * br[i].z + kr[i].w * br[i].w;
        }
        #pragma unroll
        for (int o = 16; o > 0; o >>= 1) s += __shfl_xor_sync(0xFFFFFFFFu, s, o);
        if (lane == 0) wred[warp] = s;
        __syncthreads();
        if (tid == 0) {
            float kb = 0.f;
            #pragma unroll
            for (int w = 0; w < 8; w++) kb += wred[w];
            kb_sh = kb;
            a_sh  = powf(INV_N / (kb + 1e-8f), pw);
        }
        __syncthreads();
        float a = a_sh;
        float* Trow = out + ((size_t)b * NPT + n) * NPT;
        float mx = 0.f, my = 0.f, mz = 0.f;
        #pragma unroll
        for (int i = 0; i < 4; i++) {
            int m = tid * 4 + i * 1024;
            float4 t;
            t.x = a * kr[i].x * br[i].x;
            t.y = a * kr[i].y * br[i].y;
            t.z = a * kr[i].z * br[i].z;
            t.w = a * kr[i].w * br[i].w;
            __stcs((float4*)(Trow + m), t);
            mx += t.x * cs3[m] + t.y * cs3[m + 1] + t.z * cs3[m + 2] + t.w * cs3[m + 3];
            my += t.x * cs3[NPT + m] + t.y * cs3[NPT + m + 1] + t.z * cs3[NPT + m + 2] + t.w * cs3[NPT + m + 3];
            mz += t.x * cs3[2 * NPT + m] + t.y * cs3[2 * NPT + m + 1] + t.z * cs3[2 * NPT + m + 2] + t.w * cs3[2 * NPT + m + 3];
        }
        #pragma unroll
        for (int o = 16; o > 0; o >>= 1) {
            mx += __shfl_xor_sync(0xFFFFFFFFu, mx, o);
            my += __shfl_xor_sync(0xFFFFFFFFu, my, o);
            mz += __shfl_xor_sync(0xFFFFFFFFu, mz, o);
        }
        if (lane == 0) { wred3[warp][0] = mx; wred3[warp][1] = my; wred3[warp][2] = mz; }
        __syncthreads();
        if (tid == 0) {
            float sx = 0.f, sy = 0.f, sz = 0.f;
            #pragma unroll
            for (int w = 0; w < 8; w++) { sx += wred3[w][0]; sy += wred3[w][1]; sz += wred3[w][2]; }
            float rs = a_sh * kb_sh;
            float inv = 1.0f / (rs + 1e-8f);
            float* mout = out + (size_t)NB * NPT * NPT + ((size_t)b * NPT + n) * 3;
            mout[0] = sx * inv; mout[1] = sy * inv; mout[2] = sz * inv;
            g_rowsum[b * NPT + n] = rs;
        }
        __syncthreads();
    }
}

// -------- 6) weighted Kabsch per batch --------
__device__ __forceinline__ float block_reduce(float v, float* red) {
    int tid = threadIdx.x;
    red[tid] = v;
    __syncthreads();
    for (int o = 128; o > 0; o >>= 1) {
        if (tid < o) red[tid] += red[tid + o];
        __syncthreads();
    }
    float r = red[0];
    __syncthreads();
    return r;
}

__global__ __launch_bounds__(256) void rigid_kernel(const float* __restrict__ coords,
                                                    float* __restrict__ out) {
    __shared__ float red[256];
    int b = blockIdx.x, tid = threadIdx.x;
    const float* c1    = coords + (size_t)b * NPT * 4;
    const float* match = out + (size_t)NB * NPT * NPT + (size_t)b * NPT * 3;

    float s = 0.f;
    for (int i = 0; i < 16; i++) s += g_rowsum[b * NPT + tid + i * 256];
    float wsum  = block_reduce(s, red);
    float denom = wsum + 1e-5f;

    float pc[6] = {0, 0, 0, 0, 0, 0};
    for (int i = 0; i < 16; i++) {
        int n = tid + i * 256;
        float w = g_rowsum[b * NPT + n] / denom;
        pc[0] += w * c1[n * 4 + 1]; pc[1] += w * c1[n * 4 + 2]; pc[2] += w * c1[n * 4 + 3];
        pc[3] += w * match[n * 3 + 0]; pc[4] += w * match[n * 3 + 1]; pc[5] += w * match[n * 3 + 2];
    }
    float cent[6];
    for (int k = 0; k < 6; k++) cent[k] = block_reduce(pc[k], red);

    float pcv[9] = {0};
    for (int i = 0; i < 16; i++) {
        int n = tid + i * 256;
        float w  = g_rowsum[b * NPT + n] / denom;
        float ax = c1[n * 4 + 1] - cent[0], ay = c1[n * 4 + 2] - cent[1], az = c1[n * 4 + 3] - cent[2];
        float bx = (match[n * 3 + 0] - cent[3]) * w;
        float by = (match[n * 3 + 1] - cent[4]) * w;
        float bz = (match[n * 3 + 2] - cent[5]) * w;
        pcv[0] += ax * bx; pcv[1] += ax * by; pcv[2] += ax * bz;
        pcv[3] += ay * bx; pcv[4] += ay * by; pcv[5] += ay * bz;
        pcv[6] += az * bx; pcv[7] += az * by; pcv[8] += az * bz;
    }
    float cov[9];
    for (int k = 0; k < 9; k++) cov[k] = block_reduce(pcv[k], red);

    if (tid == 0) {
        double A[3][3];
        for (int r = 0; r < 3; r++)
            for (int c = 0; c < 3; c++) A[r][c] = (double)cov[r * 3 + c];
        double S[3][3];
        for (int r = 0; r < 3; r++)
            for (int c = 0; c < 3; c++)
                S[r][c] = A[0][r] * A[0][c] + A[1][r] * A[1][c] + A[2][r] * A[2][c];
        double V[3][3] = {{1, 0, 0}, {0, 1, 0}, {0, 0, 1}};
        const int PP[3] = {0, 0, 1}, QQ[3] = {1, 2, 2};
        for (int sweep = 0; sweep < 12; sweep++) {
            for (int pr = 0; pr < 3; pr++) {
                int p = PP[pr], q = QQ[pr];
                double apq = S[p][q];
                if (fabs(apq) < 1e-300) continue;
                double theta = (S[q][q] - S[p][p]) / (2.0 * apq);
                double t = ((theta >= 0.0) ? 1.0 : -1.0) / (fabs(theta) + sqrt(theta * theta + 1.0));
                double cth = 1.0 / sqrt(t * t + 1.0), sth = t * cth;
                for (int k = 0; k < 3; k++) {
                    double skp = S[k][p], skq = S[k][q];
                    S[k][p] = cth * skp - sth * skq;
                    S[k][q] = sth * skp + cth * skq;
                }
                for (int k = 0; k < 3; k++) {
                    double spk = S[p][k], sqk = S[q][k];
                    S[p][k] = cth * spk - sth * sqk;
                    S[q][k] = sth * spk + cth * sqk;
                }
                for (int k = 0; k < 3; k++) {
                    double vkp = V[k][p], vkq = V[k][q];
                    V[k][p] = cth * vkp - sth * vkq;
                    V[k][q] = sth * vkp + cth * vkq;
                }
            }
        }
        double ev[3] = {S[0][0], S[1][1], S[2][2]};
        int id[3] = {0, 1, 2};
        for (int i = 0; i < 2; i++)
            for (int j = 0; j < 2 - i; j++)
                if (ev[id[j]] < ev[id[j + 1]]) { int tmp = id[j]; id[j] = id[j + 1]; id[j + 1] = tmp; }
        double sv[3], Vs[3][3], U[3][3];
        for (int i = 0; i < 3; i++) {
            sv[i] = sqrt(fmax(ev[id[i]], 0.0));
            for (int r = 0; r < 3; r++) Vs[r][i] = V[r][id[i]];
        }
        for (int i = 0; i < 3; i++) {
            double inv = (sv[i] > 0.0) ? 1.0 / sv[i] : 0.0;
            for (int r = 0; r < 3; r++)
                U[r][i] = (A[r][0] * Vs[0][i] + A[r][1] * Vs[1][i] + A[r][2] * Vs[2][i]) * inv;
        }
        double detA = A[0][0] * (A[1][1] * A[2][2] - A[1][2] * A[2][1])
                    - A[0][1] * (A[1][0] * A[2][2] - A[1][2] * A[2][0])
                    + A[0][2] * (A[1][0] * A[2][1] - A[1][1] * A[2][0]);
        if (!(detA > 0.0)) { Vs[0][2] = -Vs[0][2]; Vs[1][2] = -Vs[1][2]; Vs[2][2] = -Vs[2][2]; }
        double R[3][3];
        for (int r = 0; r < 3; r++)
            for (int c = 0; c < 3; c++)
                R[r][c] = Vs[r][0] * U[c][0] + Vs[r][1] * U[c][1] + Vs[r][2] * U[c][2];
        float* tout = out + (size_t)NB * NPT * NPT + (size_t)NB * NPT * 3 + b * 12;
        for (int r = 0; r < 3; r++) {
            double tr = -(R[r][0] * cent[0] + R[r][1] * cent[1] + R[r][2] * cent[2]) + cent[3 + r];
            tout[r * 4 + 0] = (float)R[r][0];
            tout[r * 4 + 1] = (float)R[r][1];
            tout[r * 4 + 2] = (float)R[r][2];
            tout[r * 4 + 3] = (float)tr;
        }
    }
}

extern "C" void kernel_launch(void* const* d_in, const int* in_sizes, int n_in,
                              void* d_out, int out_size) {
    const float* pf     = (const float*)d_in[0];
    const float* coords = (const float*)d_in[1];
    const float* gamma  = (const float*)d_in[2];
    const float* epsv   = (const float*)d_in[3];
    float* out = (float*)d_out;

    cudaFuncSetAttribute(gemm_mma_kernel,
                         cudaFuncAttributeMaxDynamicSharedMemorySize, SMEM_DYN);
    cudaFuncSetAttribute(prep_kernel,
                         cudaFuncAttributeMaxDynamicSharedMemorySize, PRE_SMEM);
    cudaFuncSetAttribute(kb_final_kernel,
                         cudaFuncAttributeMaxDynamicSharedMemorySize, FIN_SMEM);

    prep_kernel<<<dim3(NPT / 32, 2 * NB), 256, PRE_SMEM>>>(pf);                   // 0
    gemm_mma_kernel<<<dim3(NPT / 128, NPT / 128, NB), 256, SMEM_DYN>>>(epsv);     // 1
    update_b_kernel<32><<<dim3(NPT / 256, NB), 256>>>(gamma, epsv);               // 2 -> b1
    for (int it = 0; it < 4; it++) {
        fused_kb_kta_kernel<<<dim3(NPT / 32, NB), 256>>>(gamma, epsv);            // 3 on it=0 (profiled)
        update_b_kernel<128><<<dim3(NPT / 256, NB), 256>>>(gamma, epsv);          // -> b2..b5
    }
    kb_final_kernel<<<dim3(NPT / 4, NB), 256, FIN_SMEM>>>(gamma, epsv, coords, out);
    rigid_kernel<<<NB, 256>>>(coords, out);
}